// round 1
// baseline (speedup 1.0000x reference)
#include <cuda_runtime.h>
#include <math.h>

#define N_NODES 50000
#define N_EDGES 800000
#define ET      850000   // edges + self loops
#define FIN     128
#define HID     64
#define NGRAPH  512
#define NEG_SLOPE 0.2f

// ---------------- scratch (device globals, no allocation) ----------------
__device__ float g_h[N_NODES * HID];       // transformed features of current layer
__device__ float g_bufA[N_NODES * HID];    // layer outputs (ping)
__device__ float g_bufB[N_NODES * HID];    // layer outputs (pong)
__device__ float g_alpha[ET];
__device__ float g_ssum[N_NODES];
__device__ float g_asrc[N_NODES];
__device__ float g_adst[N_NODES];
__device__ int   g_src[ET];
__device__ int   g_dst[ET];
__device__ float g_eatt[ET];
__device__ float g_pooled[NGRAPH * HID];
__device__ float g_cnt[NGRAPH];
__device__ float g_scal[8];   // [0]=edge_weight sum, [1..3]=c per layer

// ---------------- small init kernels ----------------
__global__ void k_zero() {
    int i = blockIdx.x * blockDim.x + threadIdx.x;
    int tot = NGRAPH * HID;
    if (i < tot) g_pooled[i] = 0.f;
    if (i < NGRAPH) g_cnt[i] = 0.f;
    if (i == 0) g_scal[0] = 0.f;
}

// per-layer scalar c = dot(We, ae)   (We is [1,HID])
__global__ void k_c(const float* __restrict__ We0, const float* __restrict__ ae0,
                    const float* __restrict__ We1, const float* __restrict__ ae1,
                    const float* __restrict__ We2, const float* __restrict__ ae2) {
    __shared__ float r[64];
    int l = blockIdx.x;
    int j = threadIdx.x;
    const float* We = (l == 0) ? We0 : (l == 1) ? We1 : We2;
    const float* ae = (l == 0) ? ae0 : (l == 1) ? ae1 : ae2;
    r[j] = We[j] * ae[j];
    __syncthreads();
    for (int off = 32; off > 0; off >>= 1) {
        if (j < off) r[j] += r[j + off];
        __syncthreads();
    }
    if (j == 0) g_scal[1 + l] = r[0];
}

// sum of edge_weight (for self-loop fill value = mean)
__global__ void k_mean(const float* __restrict__ ew) {
    __shared__ float sm[256];
    float acc = 0.f;
    for (int i = blockIdx.x * blockDim.x + threadIdx.x; i < N_EDGES;
         i += gridDim.x * blockDim.x)
        acc += ew[i];
    sm[threadIdx.x] = acc;
    __syncthreads();
    for (int off = 128; off > 0; off >>= 1) {
        if (threadIdx.x < off) sm[threadIdx.x] += sm[threadIdx.x + off];
        __syncthreads();
    }
    if (threadIdx.x == 0) atomicAdd(&g_scal[0], sm[0]);
}

// build combined edge arrays (edges + self loops), eattr with mean fill
__global__ void k_build(const int* __restrict__ eidx, const float* __restrict__ ew) {
    int e = blockIdx.x * blockDim.x + threadIdx.x;
    if (e >= ET) return;
    if (e < N_EDGES) {
        g_src[e] = eidx[e];
        g_dst[e] = eidx[N_EDGES + e];
        g_eatt[e] = ew[e];
    } else {
        int n = e - N_EDGES;
        g_src[e] = n;
        g_dst[e] = n;
        g_eatt[e] = g_scal[0] * (1.0f / (float)N_EDGES);
    }
}

// ---------------- per-layer kernels ----------------
// GEMM h = X@W  (+ relu on input), per-node attention logits, init out=bias, ssum=0.
// 4 nodes per block, 256 threads (64 per node).
__global__ void k_gemm(const float* __restrict__ Xext, int in_sel, int out_sel,
                       int Fin, const float* __restrict__ W,
                       const float* __restrict__ as_, const float* __restrict__ ad_,
                       const float* __restrict__ bias, int relu_in) {
    __shared__ float xs[4][FIN];
    __shared__ float r1[256];
    __shared__ float r2[256];
    const float* X = (in_sel == 0) ? Xext : (in_sel == 1) ? g_bufA : g_bufB;
    float* out = (out_sel == 1) ? g_bufA : g_bufB;

    int t = threadIdx.x;
    int ln = t >> 6;        // 0..3
    int j  = t & 63;        // output feature
    int n  = blockIdx.x * 4 + ln;   // N_NODES % 4 == 0

    for (int k = j; k < Fin; k += 64) {
        float v = X[(size_t)n * Fin + k];
        if (relu_in) v = fmaxf(v, 0.f);
        xs[ln][k] = v;
    }
    __syncthreads();

    float acc = 0.f;
    #pragma unroll 16
    for (int k = 0; k < Fin; k++)
        acc = fmaf(xs[ln][k], W[k * HID + j], acc);

    g_h[(size_t)n * HID + j] = acc;
    out[(size_t)n * HID + j] = bias[j];
    r1[t] = acc * as_[j];
    r2[t] = acc * ad_[j];
    __syncthreads();
    #pragma unroll
    for (int off = 32; off > 0; off >>= 1) {
        if (j < off) { r1[t] += r1[t + off]; r2[t] += r2[t + off]; }
        __syncthreads();
    }
    if (j == 0) {
        g_asrc[n] = r1[t];
        g_adst[n] = r2[t];
        g_ssum[n] = 0.f;
    }
}

// alpha = exp(leakyrelu(asrc[src]+adst[dst]+eatt*c)); ssum[dst] += alpha
__global__ void k_alpha(int layer) {
    int e = blockIdx.x * blockDim.x + threadIdx.x;
    if (e >= ET) return;
    float c = g_scal[1 + layer];
    int s = g_src[e];
    int d = g_dst[e];
    float al = g_asrc[s] + g_adst[d] + g_eatt[e] * c;
    al = fmaxf(al, 0.f) + NEG_SLOPE * fminf(al, 0.f);
    float v = expf(al);
    g_alpha[e] = v;
    atomicAdd(&g_ssum[d], v);
}

// out[dst] += h[src] * alpha/(ssum[dst]+eps), one warp per edge (2 floats/lane)
__global__ void k_scatter(int out_sel) {
    float* out = (out_sel == 1) ? g_bufA : g_bufB;
    int gt = blockIdx.x * blockDim.x + threadIdx.x;
    int e = gt >> 5;
    int lane = gt & 31;
    if (e >= ET) return;
    int s, d; float w;
    if (lane == 0) {
        s = g_src[e];
        d = g_dst[e];
        w = g_alpha[e] / (g_ssum[d] + 1e-16f);
    }
    s = __shfl_sync(0xffffffff, s, 0);
    d = __shfl_sync(0xffffffff, d, 0);
    w = __shfl_sync(0xffffffff, w, 0);
    float2 hv = *(const float2*)&g_h[(size_t)s * HID + lane * 2];
    atomicAdd(&out[(size_t)d * HID + lane * 2],     hv.x * w);
    atomicAdd(&out[(size_t)d * HID + lane * 2 + 1], hv.y * w);
}

// ---------------- readout ----------------
// warp per node: pooled[batch[n]] += feat[n]; cnt[batch[n]]++
__global__ void k_pool(int in_sel, const int* __restrict__ batch) {
    const float* feat = (in_sel == 1) ? g_bufA : g_bufB;
    int gt = blockIdx.x * blockDim.x + threadIdx.x;
    int n = gt >> 5;
    int lane = gt & 31;
    if (n >= N_NODES) return;
    int g;
    if (lane == 0) g = batch[n];
    g = __shfl_sync(0xffffffff, g, 0);
    float2 hv = *(const float2*)&feat[(size_t)n * HID + lane * 2];
    atomicAdd(&g_pooled[(size_t)g * HID + lane * 2],     hv.x);
    atomicAdd(&g_pooled[(size_t)g * HID + lane * 2 + 1], hv.y);
    if (lane == 0) atomicAdd(&g_cnt[g], 1.f);
}

// block (64 threads) per graph: sigmoid(mean @ lin_w + lin_b)
__global__ void k_read(const float* __restrict__ lin_w,
                       const float* __restrict__ lin_b, float* __restrict__ outp) {
    __shared__ float r[64];
    int g = blockIdx.x;
    int j = threadIdx.x;
    float cnt = fmaxf(g_cnt[g], 1.f);
    r[j] = (g_pooled[(size_t)g * HID + j] / cnt) * lin_w[j];
    __syncthreads();
    for (int off = 32; off > 0; off >>= 1) {
        if (j < off) r[j] += r[j + off];
        __syncthreads();
    }
    if (j == 0) {
        float v = r[0] + lin_b[0];
        outp[g] = 1.f / (1.f + expf(-v));
    }
}

// ---------------- launch ----------------
extern "C" void kernel_launch(void* const* d_in, const int* in_sizes, int n_in,
                              void* d_out, int out_size) {
    const float* x     = (const float*)d_in[0];
    const int*   eidx  = (const int*)  d_in[1];
    const float* ew    = (const float*)d_in[2];
    const int*   batch = (const int*)  d_in[3];
    const float* W[3]  = {(const float*)d_in[4],  (const float*)d_in[10], (const float*)d_in[16]};
    const float* as_[3]= {(const float*)d_in[5],  (const float*)d_in[11], (const float*)d_in[17]};
    const float* ad_[3]= {(const float*)d_in[6],  (const float*)d_in[12], (const float*)d_in[18]};
    const float* We[3] = {(const float*)d_in[7],  (const float*)d_in[13], (const float*)d_in[19]};
    const float* ae[3] = {(const float*)d_in[8],  (const float*)d_in[14], (const float*)d_in[20]};
    const float* b[3]  = {(const float*)d_in[9],  (const float*)d_in[15], (const float*)d_in[21]};
    const float* lin_w = (const float*)d_in[22];
    const float* lin_b = (const float*)d_in[23];
    float* outp = (float*)d_out;

    k_zero<<<(NGRAPH * HID + 255) / 256, 256>>>();
    k_c<<<3, 64>>>(We[0], ae[0], We[1], ae[1], We[2], ae[2]);
    k_mean<<<512, 256>>>(ew);
    k_build<<<(ET + 255) / 256, 256>>>(eidx, ew);

    // layer 1: in = x (ext), out = bufA
    k_gemm<<<N_NODES / 4, 256>>>(x, 0, 1, FIN, W[0], as_[0], ad_[0], b[0], 0);
    k_alpha<<<(ET + 255) / 256, 256>>>(0);
    k_scatter<<<(ET * 32 + 255) / 256, 256>>>(1);

    // layer 2: in = relu(bufA), out = bufB
    k_gemm<<<N_NODES / 4, 256>>>(nullptr, 1, 2, HID, W[1], as_[1], ad_[1], b[1], 1);
    k_alpha<<<(ET + 255) / 256, 256>>>(1);
    k_scatter<<<(ET * 32 + 255) / 256, 256>>>(2);

    // layer 3: in = relu(bufB), out = bufA
    k_gemm<<<N_NODES / 4, 256>>>(nullptr, 2, 1, HID, W[2], as_[2], ad_[2], b[2], 1);
    k_alpha<<<(ET + 255) / 256, 256>>>(2);
    k_scatter<<<(ET * 32 + 255) / 256, 256>>>(1);

    // readout from bufA
    k_pool<<<(N_NODES * 32 + 255) / 256, 256>>>(1, batch);
    k_read<<<NGRAPH, 64>>>(lin_w, lin_b, outp);
}

// round 2
// speedup vs baseline: 1.3661x; 1.3661x over previous
#include <cuda_runtime.h>
#include <math.h>

#define N_NODES 50000
#define N_EDGES 800000
#define ET      850000   // edges + self loops
#define FIN     128
#define HID     64
#define NGRAPH  512
#define NEG_SLOPE 0.2f

// ---------------- scratch (device globals, no allocation) ----------------
__device__ float g_h[N_NODES * HID];       // transformed features of current layer
__device__ float g_accA[N_NODES * HID];    // unnormalized aggregation (ping)
__device__ float g_accB[N_NODES * HID];    // unnormalized aggregation (pong)
__device__ float g_ssumA[N_NODES];
__device__ float g_ssumB[N_NODES];
__device__ float g_asrc[N_NODES];
__device__ float g_adst[N_NODES];
__device__ int   g_src[ET];
__device__ int   g_dst[ET];
__device__ float g_eatt[ET];
__device__ float g_pooled[NGRAPH * HID];
__device__ float g_cnt[NGRAPH];
__device__ float g_scal[8];   // [0]=edge_weight sum, [1..3]=c per layer

// ---------------- small init kernels ----------------
__global__ void k_zero() {
    int i = blockIdx.x * blockDim.x + threadIdx.x;
    int tot = NGRAPH * HID;
    if (i < tot) g_pooled[i] = 0.f;
    if (i < NGRAPH) g_cnt[i] = 0.f;
    if (i == 0) g_scal[0] = 0.f;
}

// per-layer scalar c = dot(We, ae)   (We is [1,HID])
__global__ void k_c(const float* __restrict__ We0, const float* __restrict__ ae0,
                    const float* __restrict__ We1, const float* __restrict__ ae1,
                    const float* __restrict__ We2, const float* __restrict__ ae2) {
    __shared__ float r[64];
    int l = blockIdx.x;
    int j = threadIdx.x;
    const float* We = (l == 0) ? We0 : (l == 1) ? We1 : We2;
    const float* ae = (l == 0) ? ae0 : (l == 1) ? ae1 : ae2;
    r[j] = We[j] * ae[j];
    __syncthreads();
    for (int off = 32; off > 0; off >>= 1) {
        if (j < off) r[j] += r[j + off];
        __syncthreads();
    }
    if (j == 0) g_scal[1 + l] = r[0];
}

// sum of edge_weight (for self-loop fill value = mean)
__global__ void k_mean(const float* __restrict__ ew) {
    __shared__ float sm[256];
    float acc = 0.f;
    for (int i = blockIdx.x * blockDim.x + threadIdx.x; i < N_EDGES;
         i += gridDim.x * blockDim.x)
        acc += ew[i];
    sm[threadIdx.x] = acc;
    __syncthreads();
    for (int off = 128; off > 0; off >>= 1) {
        if (threadIdx.x < off) sm[threadIdx.x] += sm[threadIdx.x + off];
        __syncthreads();
    }
    if (threadIdx.x == 0) atomicAdd(&g_scal[0], sm[0]);
}

// build combined edge arrays (edges + self loops), eattr with mean fill
__global__ void k_build(const int* __restrict__ eidx, const float* __restrict__ ew) {
    int e = blockIdx.x * blockDim.x + threadIdx.x;
    if (e >= ET) return;
    if (e < N_EDGES) {
        g_src[e] = eidx[e];
        g_dst[e] = eidx[N_EDGES + e];
        g_eatt[e] = ew[e];
    } else {
        int n = e - N_EDGES;
        g_src[e] = n;
        g_dst[e] = n;
        g_eatt[e] = g_scal[0] * (1.0f / (float)N_EDGES);
    }
}

// ---------------- per-layer kernels ----------------
// Fused: normalize previous layer's aggregation (acc/ssum + bias_prev, relu),
// GEMM h = X@W, per-node attention logits, zero current acc & ssum.
// 4 nodes per block, 256 threads (64 per node).
__global__ void k_gemm(const float* __restrict__ Xext, int in_sel, int out_sel,
                       int Fin, const float* __restrict__ W,
                       const float* __restrict__ as_, const float* __restrict__ ad_,
                       const float* __restrict__ bias_prev) {
    __shared__ float xs[4][FIN];
    __shared__ float r1[256];
    __shared__ float r2[256];
    const float* accP = (in_sel == 1) ? g_accA : g_accB;
    const float* ssP  = (in_sel == 1) ? g_ssumA : g_ssumB;
    float* accO = (out_sel == 1) ? g_accA : g_accB;
    float* ssO  = (out_sel == 1) ? g_ssumA : g_ssumB;

    int t = threadIdx.x;
    int ln = t >> 6;        // 0..3
    int j  = t & 63;        // output feature
    int n  = blockIdx.x * 4 + ln;   // N_NODES % 4 == 0

    if (in_sel == 0) {
        for (int k = j; k < FIN; k += 64)
            xs[ln][k] = Xext[(size_t)n * FIN + k];
    } else {
        float inv = 1.f / (ssP[n] + 1e-16f);
        xs[ln][j] = fmaxf(accP[(size_t)n * HID + j] * inv + bias_prev[j], 0.f);
    }
    __syncthreads();

    float acc = 0.f;
    if (Fin == FIN) {
        #pragma unroll
        for (int k = 0; k < FIN; k++)
            acc = fmaf(xs[ln][k], W[k * HID + j], acc);
    } else {
        #pragma unroll
        for (int k = 0; k < HID; k++)
            acc = fmaf(xs[ln][k], W[k * HID + j], acc);
    }

    g_h[(size_t)n * HID + j] = acc;
    accO[(size_t)n * HID + j] = 0.f;
    r1[t] = acc * as_[j];
    r2[t] = acc * ad_[j];
    __syncthreads();
    #pragma unroll
    for (int off = 32; off > 0; off >>= 1) {
        if (j < off) { r1[t] += r1[t + off]; r2[t] += r2[t + off]; }
        __syncthreads();
    }
    if (j == 0) {
        g_asrc[n] = r1[t];
        g_adst[n] = r2[t];
        ssO[n] = 0.f;
    }
}

// Fused edge pass: alpha = exp(leakyrelu(asrc[src]+adst[dst]+eatt*c));
// ssum[dst] += alpha;  acc[dst] += h[src] * alpha  (unnormalized).
// 16 threads per edge, one red.v4 per lane.
__global__ void k_edge(int layer, int acc_sel) {
    float* acc  = (acc_sel == 1) ? g_accA : g_accB;
    float* ssum = (acc_sel == 1) ? g_ssumA : g_ssumB;
    int gt = blockIdx.x * blockDim.x + threadIdx.x;
    int e = gt >> 4;            // ET*16 is an exact multiple of 256 -> no tail
    int sub = gt & 15;
    int lane = threadIdx.x & 31;
    int base = lane & 16;       // base lane of this 16-group within the warp

    int s, d;
    float alpha;
    if (sub == 0) {
        s = g_src[e];
        d = g_dst[e];
        float c = g_scal[1 + layer];
        float al = g_asrc[s] + g_adst[d] + g_eatt[e] * c;
        al = fmaxf(al, 0.f) + NEG_SLOPE * fminf(al, 0.f);
        alpha = __expf(al);
        atomicAdd(&ssum[d], alpha);
    }
    s = __shfl_sync(0xffffffffu, s, base);
    d = __shfl_sync(0xffffffffu, d, base);
    alpha = __shfl_sync(0xffffffffu, alpha, base);

    float4 hv = *reinterpret_cast<const float4*>(&g_h[(size_t)s * HID + (sub << 2)]);
    float* p = &acc[(size_t)d * HID + (sub << 2)];
    asm volatile("red.global.add.v4.f32 [%0], {%1,%2,%3,%4};"
                 :: "l"(p), "f"(hv.x * alpha), "f"(hv.y * alpha),
                    "f"(hv.z * alpha), "f"(hv.w * alpha)
                 : "memory");
}

// ---------------- readout ----------------
// 16 threads per node: pooled[batch[n]] += acc[n]/ssum[n] + b3; cnt[batch[n]]++
__global__ void k_pool(int acc_sel, const int* __restrict__ batch,
                       const float* __restrict__ bias) {
    const float* acc  = (acc_sel == 1) ? g_accA : g_accB;
    const float* ssum = (acc_sel == 1) ? g_ssumA : g_ssumB;
    int gt = blockIdx.x * blockDim.x + threadIdx.x;
    int n = gt >> 4;            // N_NODES*16 is an exact multiple of 256
    int sub = gt & 15;
    if (n >= N_NODES) return;
    int g = batch[n];
    float inv = 1.f / (ssum[n] + 1e-16f);
    int o = sub << 2;
    float4 v = *reinterpret_cast<const float4*>(&acc[(size_t)n * HID + o]);
    float4 b = *reinterpret_cast<const float4*>(&bias[o]);
    float* p = &g_pooled[(size_t)g * HID + o];
    asm volatile("red.global.add.v4.f32 [%0], {%1,%2,%3,%4};"
                 :: "l"(p), "f"(v.x * inv + b.x), "f"(v.y * inv + b.y),
                    "f"(v.z * inv + b.z), "f"(v.w * inv + b.w)
                 : "memory");
    if (sub == 0) atomicAdd(&g_cnt[g], 1.f);
}

// block (64 threads) per graph: sigmoid(mean @ lin_w + lin_b)
__global__ void k_read(const float* __restrict__ lin_w,
                       const float* __restrict__ lin_b, float* __restrict__ outp) {
    __shared__ float r[64];
    int g = blockIdx.x;
    int j = threadIdx.x;
    float cnt = fmaxf(g_cnt[g], 1.f);
    r[j] = (g_pooled[(size_t)g * HID + j] / cnt) * lin_w[j];
    __syncthreads();
    for (int off = 32; off > 0; off >>= 1) {
        if (j < off) r[j] += r[j + off];
        __syncthreads();
    }
    if (j == 0) {
        float v = r[0] + lin_b[0];
        outp[g] = 1.f / (1.f + expf(-v));
    }
}

// ---------------- launch ----------------
extern "C" void kernel_launch(void* const* d_in, const int* in_sizes, int n_in,
                              void* d_out, int out_size) {
    const float* x     = (const float*)d_in[0];
    const int*   eidx  = (const int*)  d_in[1];
    const float* ew    = (const float*)d_in[2];
    const int*   batch = (const int*)  d_in[3];
    const float* W[3]  = {(const float*)d_in[4],  (const float*)d_in[10], (const float*)d_in[16]};
    const float* as_[3]= {(const float*)d_in[5],  (const float*)d_in[11], (const float*)d_in[17]};
    const float* ad_[3]= {(const float*)d_in[6],  (const float*)d_in[12], (const float*)d_in[18]};
    const float* We[3] = {(const float*)d_in[7],  (const float*)d_in[13], (const float*)d_in[19]};
    const float* ae[3] = {(const float*)d_in[8],  (const float*)d_in[14], (const float*)d_in[20]};
    const float* b[3]  = {(const float*)d_in[9],  (const float*)d_in[15], (const float*)d_in[21]};
    const float* lin_w = (const float*)d_in[22];
    const float* lin_b = (const float*)d_in[23];
    float* outp = (float*)d_out;

    k_zero<<<(NGRAPH * HID + 255) / 256, 256>>>();
    k_c<<<3, 64>>>(We[0], ae[0], We[1], ae[1], We[2], ae[2]);
    k_mean<<<512, 256>>>(ew);
    k_build<<<(ET + 255) / 256, 256>>>(eidx, ew);

    const int EDGE_BLOCKS = (ET * 16) / 256;   // 53125, exact

    // layer 1: in = x (ext), out acc = A
    k_gemm<<<N_NODES / 4, 256>>>(x, 0, 1, FIN, W[0], as_[0], ad_[0], nullptr);
    k_edge<<<EDGE_BLOCKS, 256>>>(0, 1);

    // layer 2: in = norm(A)+b1 relu, out acc = B
    k_gemm<<<N_NODES / 4, 256>>>(nullptr, 1, 2, HID, W[1], as_[1], ad_[1], b[0]);
    k_edge<<<EDGE_BLOCKS, 256>>>(1, 2);

    // layer 3: in = norm(B)+b2 relu, out acc = A
    k_gemm<<<N_NODES / 4, 256>>>(nullptr, 2, 1, HID, W[2], as_[2], ad_[2], b[1]);
    k_edge<<<EDGE_BLOCKS, 256>>>(2, 1);

    // readout: norm(A)+b3 -> mean pool -> linear -> sigmoid
    k_pool<<<(N_NODES * 16) / 256, 256>>>(1, batch, b[2]);
    k_read<<<NGRAPH, 64>>>(lin_w, lin_b, outp);
}

// round 3
// speedup vs baseline: 2.3916x; 1.7507x over previous
#include <cuda_runtime.h>
#include <math.h>

#define NN   50000
#define NE   800000
#define ET   850000
#define FIN  128
#define HID  64
#define NG   512
#define SLOPE 0.2f

// ---------------- scratch ----------------
__device__ float g_h[NN * HID];
__device__ float g_out[NN * HID];     // normalized layer output
__device__ float g_asrc[NN];
__device__ float g_adst[NN];
__device__ int   g_cnt[NN];
__device__ int   g_rofs[NN + 1];
__device__ int   g_pos[NN];
__device__ int   g_esrc[ET];          // src permuted by dst
__device__ float g_eatt[ET];          // eattr permuted by dst
__device__ float g_pooled[NG * HID];
__device__ float g_gcnt[NG];
__device__ float g_scal[8];           // [0]=sum(ew), [1..3]=c per layer
__device__ int   g_bsum[256];
__device__ int   g_bpre[256];

// ---------------- setup ----------------
__global__ void k_zero() {
    int i = blockIdx.x * blockDim.x + threadIdx.x;
    if (i < NN) g_cnt[i] = 0;
    if (i < NG * HID) g_pooled[i] = 0.f;
    if (i < NG) g_gcnt[i] = 0.f;
    if (i == 0) g_scal[0] = 0.f;
}

__global__ void k_c(const float* __restrict__ We0, const float* __restrict__ ae0,
                    const float* __restrict__ We1, const float* __restrict__ ae1,
                    const float* __restrict__ We2, const float* __restrict__ ae2) {
    __shared__ float r[64];
    int l = blockIdx.x, j = threadIdx.x;
    const float* We = (l == 0) ? We0 : (l == 1) ? We1 : We2;
    const float* ae = (l == 0) ? ae0 : (l == 1) ? ae1 : ae2;
    r[j] = We[j] * ae[j];
    __syncthreads();
    for (int off = 32; off > 0; off >>= 1) {
        if (j < off) r[j] += r[j + off];
        __syncthreads();
    }
    if (j == 0) g_scal[1 + l] = r[0];
}

__global__ void k_mean(const float* __restrict__ ew) {
    __shared__ float sm[256];
    float acc = 0.f;
    for (int i = blockIdx.x * blockDim.x + threadIdx.x; i < NE;
         i += gridDim.x * blockDim.x)
        acc += ew[i];
    sm[threadIdx.x] = acc;
    __syncthreads();
    for (int off = 128; off > 0; off >>= 1) {
        if (threadIdx.x < off) sm[threadIdx.x] += sm[threadIdx.x + off];
        __syncthreads();
    }
    if (threadIdx.x == 0) atomicAdd(&g_scal[0], sm[0]);
}

__global__ void k_hist(const int* __restrict__ eidx) {
    int e = blockIdx.x * blockDim.x + threadIdx.x;
    if (e >= ET) return;
    int d = (e < NE) ? eidx[NE + e] : (e - NE);
    atomicAdd(&g_cnt[d], 1);
}

// scan stage 1: per-block sums of 256 counts
__global__ void k_s1() {
    __shared__ int sh[256];
    int t = threadIdx.x;
    int i = blockIdx.x * 256 + t;
    sh[t] = (i < NN) ? g_cnt[i] : 0;
    __syncthreads();
    for (int off = 128; off > 0; off >>= 1) {
        if (t < off) sh[t] += sh[t + off];
        __syncthreads();
    }
    if (t == 0) g_bsum[blockIdx.x] = sh[0];
}

// scan stage 2: exclusive scan of block sums (nblocks <= 256)
__global__ void k_s2(int nb) {
    __shared__ int sh[256];
    int t = threadIdx.x;
    int v = (t < nb) ? g_bsum[t] : 0;
    sh[t] = v;
    __syncthreads();
    for (int off = 1; off < 256; off <<= 1) {
        int x = (t >= off) ? sh[t - off] : 0;
        __syncthreads();
        sh[t] += x;
        __syncthreads();
    }
    if (t < nb) g_bpre[t] = sh[t] - v;   // exclusive
}

// scan stage 3: per-block exclusive scan + offset -> rofs, pos
__global__ void k_s3() {
    __shared__ int sh[256];
    int t = threadIdx.x;
    int i = blockIdx.x * 256 + t;
    int v = (i < NN) ? g_cnt[i] : 0;
    sh[t] = v;
    __syncthreads();
    for (int off = 1; off < 256; off <<= 1) {
        int x = (t >= off) ? sh[t - off] : 0;
        __syncthreads();
        sh[t] += x;
        __syncthreads();
    }
    if (i < NN) {
        int r = g_bpre[blockIdx.x] + sh[t] - v;   // exclusive prefix
        g_rofs[i] = r;
        g_pos[i] = r;
    }
    if (blockIdx.x == 0 && t == 0) g_rofs[NN] = ET;
}

__global__ void k_scat(const int* __restrict__ eidx, const float* __restrict__ ew) {
    int e = blockIdx.x * blockDim.x + threadIdx.x;
    if (e >= ET) return;
    int s, d;
    float a;
    if (e < NE) {
        s = eidx[e];
        d = eidx[NE + e];
        a = ew[e];
    } else {
        s = d = e - NE;
        a = g_scal[0] * (1.0f / (float)NE);
    }
    int p = atomicAdd(&g_pos[d], 1);
    g_esrc[p] = s;
    g_eatt[p] = a;
}

// ---------------- GEMM: h = relu(prev/bias)(or x) @ W ----------------
// 64 nodes per block, 256 threads, thread = 4 nodes x 4 j, k chunked by 32.
__global__ void k_gemm(const float* __restrict__ X, int ext, int Fin,
                       const float* __restrict__ W,
                       const float* __restrict__ bias_prev) {
    __shared__ float xsT[32][68];   // [k][node], padded for alignment
    __shared__ float Ws[32][64];    // [k][j]
    int t = threadIdx.x;
    int jg = t & 15;                // j = jg*4
    int ng = t >> 4;                // nodes ng*4 .. ng*4+3
    int n0 = blockIdx.x * 64;

    float4 a0 = {0,0,0,0}, a1 = {0,0,0,0}, a2 = {0,0,0,0}, a3 = {0,0,0,0};

    for (int k0 = 0; k0 < Fin; k0 += 32) {
        // load x chunk (transposed into smem)
        {
            int c = t & 31, rr = t >> 5;
            for (int r = rr; r < 64; r += 8) {
                int n = n0 + r;
                float v = 0.f;
                if (n < NN) {
                    int k = k0 + c;
                    if (ext) v = X[(size_t)n * FIN + k];
                    else     v = fmaxf(g_out[(size_t)n * HID + k] + bias_prev[k], 0.f);
                }
                xsT[c][r] = v;
            }
            int j = t & 63, r4 = t >> 6;
            for (int r = r4; r < 32; r += 4)
                Ws[r][j] = W[(size_t)(k0 + r) * HID + j];
        }
        __syncthreads();

        #pragma unroll
        for (int k = 0; k < 32; k++) {
            float4 wv = *reinterpret_cast<const float4*>(&Ws[k][jg * 4]);
            float4 xv = *reinterpret_cast<const float4*>(&xsT[k][ng * 4]);
            a0.x = fmaf(xv.x, wv.x, a0.x); a0.y = fmaf(xv.x, wv.y, a0.y);
            a0.z = fmaf(xv.x, wv.z, a0.z); a0.w = fmaf(xv.x, wv.w, a0.w);
            a1.x = fmaf(xv.y, wv.x, a1.x); a1.y = fmaf(xv.y, wv.y, a1.y);
            a1.z = fmaf(xv.y, wv.z, a1.z); a1.w = fmaf(xv.y, wv.w, a1.w);
            a2.x = fmaf(xv.z, wv.x, a2.x); a2.y = fmaf(xv.z, wv.y, a2.y);
            a2.z = fmaf(xv.z, wv.z, a2.z); a2.w = fmaf(xv.z, wv.w, a2.w);
            a3.x = fmaf(xv.w, wv.x, a3.x); a3.y = fmaf(xv.w, wv.y, a3.y);
            a3.z = fmaf(xv.w, wv.z, a3.z); a3.w = fmaf(xv.w, wv.w, a3.w);
        }
        __syncthreads();
    }

    int j = jg * 4;
    int nb = n0 + ng * 4;
    if (nb + 0 < NN) *reinterpret_cast<float4*>(&g_h[(size_t)(nb+0) * HID + j]) = a0;
    if (nb + 1 < NN) *reinterpret_cast<float4*>(&g_h[(size_t)(nb+1) * HID + j]) = a1;
    if (nb + 2 < NN) *reinterpret_cast<float4*>(&g_h[(size_t)(nb+2) * HID + j]) = a2;
    if (nb + 3 < NN) *reinterpret_cast<float4*>(&g_h[(size_t)(nb+3) * HID + j]) = a3;
}

// per-node attention logits: asrc = h.as, adst = h.ad (warp per node)
__global__ void k_att(const float* __restrict__ as_, const float* __restrict__ ad_) {
    int n = blockIdx.x * 8 + (threadIdx.x >> 5);
    int lane = threadIdx.x & 31;
    float2 hv = *reinterpret_cast<const float2*>(&g_h[(size_t)n * HID + lane * 2]);
    float2 sv = *reinterpret_cast<const float2*>(&as_[lane * 2]);
    float2 dv = *reinterpret_cast<const float2*>(&ad_[lane * 2]);
    float s = hv.x * sv.x + hv.y * sv.y;
    float d = hv.x * dv.x + hv.y * dv.y;
    #pragma unroll
    for (int off = 16; off > 0; off >>= 1) {
        s += __shfl_xor_sync(0xffffffffu, s, off);
        d += __shfl_xor_sync(0xffffffffu, d, off);
    }
    if (lane == 0) { g_asrc[n] = s; g_adst[n] = d; }
}

// ---------------- segmented aggregation: warp per dst node ----------------
__global__ void k_agg(int layer) {
    int n = blockIdx.x * 8 + (threadIdx.x >> 5);
    int lane = threadIdx.x & 31;
    int start = g_rofs[n], end = g_rofs[n + 1];
    float c = g_scal[1 + layer];
    float adstn = g_adst[n];

    float accx = 0.f, accy = 0.f, ssum = 0.f;

    for (int base = start; base < end; base += 32) {
        int i = base + lane;
        int s_l = 0;
        float alpha = 0.f;
        if (i < end) {
            s_l = g_esrc[i];
            float al = g_asrc[s_l] + adstn + g_eatt[i] * c;
            al = fmaxf(al, 0.f) + SLOPE * fminf(al, 0.f);
            alpha = __expf(al);
        }
        ssum += alpha;
        int cnt = min(32, end - base);
        int j = 0;
        for (; j + 4 <= cnt; j += 4) {
            #pragma unroll
            for (int u = 0; u < 4; u++) {
                int   sj = __shfl_sync(0xffffffffu, s_l,   j + u);
                float aj = __shfl_sync(0xffffffffu, alpha, j + u);
                float2 hv = *reinterpret_cast<const float2*>(
                    &g_h[(size_t)sj * HID + lane * 2]);
                accx = fmaf(aj, hv.x, accx);
                accy = fmaf(aj, hv.y, accy);
            }
        }
        for (; j < cnt; j++) {
            int   sj = __shfl_sync(0xffffffffu, s_l,   j);
            float aj = __shfl_sync(0xffffffffu, alpha, j);
            float2 hv = *reinterpret_cast<const float2*>(
                &g_h[(size_t)sj * HID + lane * 2]);
            accx = fmaf(aj, hv.x, accx);
            accy = fmaf(aj, hv.y, accy);
        }
    }

    #pragma unroll
    for (int off = 16; off > 0; off >>= 1)
        ssum += __shfl_xor_sync(0xffffffffu, ssum, off);
    float inv = 1.f / (ssum + 1e-16f);
    float2 o = {accx * inv, accy * inv};
    *reinterpret_cast<float2*>(&g_out[(size_t)n * HID + lane * 2]) = o;
}

// ---------------- readout ----------------
__global__ void k_pool(const int* __restrict__ batch, const float* __restrict__ bias) {
    int gt = blockIdx.x * blockDim.x + threadIdx.x;
    int n = gt >> 4;
    int sub = gt & 15;
    if (n >= NN) return;
    int g = batch[n];
    int o = sub << 2;
    float4 v = *reinterpret_cast<const float4*>(&g_out[(size_t)n * HID + o]);
    float4 b = *reinterpret_cast<const float4*>(&bias[o]);
    float* p = &g_pooled[(size_t)g * HID + o];
    asm volatile("red.global.add.v4.f32 [%0], {%1,%2,%3,%4};"
                 :: "l"(p), "f"(v.x + b.x), "f"(v.y + b.y),
                    "f"(v.z + b.z), "f"(v.w + b.w)
                 : "memory");
    if (sub == 0) atomicAdd(&g_gcnt[g], 1.f);
}

__global__ void k_read(const float* __restrict__ lin_w,
                       const float* __restrict__ lin_b, float* __restrict__ outp) {
    __shared__ float r[64];
    int g = blockIdx.x, j = threadIdx.x;
    float cnt = fmaxf(g_gcnt[g], 1.f);
    r[j] = (g_pooled[(size_t)g * HID + j] / cnt) * lin_w[j];
    __syncthreads();
    for (int off = 32; off > 0; off >>= 1) {
        if (j < off) r[j] += r[j + off];
        __syncthreads();
    }
    if (j == 0) {
        float v = r[0] + lin_b[0];
        outp[g] = 1.f / (1.f + expf(-v));
    }
}

// ---------------- launch ----------------
extern "C" void kernel_launch(void* const* d_in, const int* in_sizes, int n_in,
                              void* d_out, int out_size) {
    const float* x     = (const float*)d_in[0];
    const int*   eidx  = (const int*)  d_in[1];
    const float* ew    = (const float*)d_in[2];
    const int*   batch = (const int*)  d_in[3];
    const float* W[3]  = {(const float*)d_in[4],  (const float*)d_in[10], (const float*)d_in[16]};
    const float* as_[3]= {(const float*)d_in[5],  (const float*)d_in[11], (const float*)d_in[17]};
    const float* ad_[3]= {(const float*)d_in[6],  (const float*)d_in[12], (const float*)d_in[18]};
    const float* We[3] = {(const float*)d_in[7],  (const float*)d_in[13], (const float*)d_in[19]};
    const float* ae[3] = {(const float*)d_in[8],  (const float*)d_in[14], (const float*)d_in[20]};
    const float* b[3]  = {(const float*)d_in[9],  (const float*)d_in[15], (const float*)d_in[21]};
    const float* lin_w = (const float*)d_in[22];
    const float* lin_b = (const float*)d_in[23];
    float* outp = (float*)d_out;

    const int NB_SCAN = (NN + 255) / 256;     // 196

    k_zero<<<(NN + 255) / 256, 256>>>();
    k_c<<<3, 64>>>(We[0], ae[0], We[1], ae[1], We[2], ae[2]);
    k_mean<<<512, 256>>>(ew);
    k_hist<<<(ET + 255) / 256, 256>>>(eidx);
    k_s1<<<NB_SCAN, 256>>>();
    k_s2<<<1, 256>>>(NB_SCAN);
    k_s3<<<NB_SCAN, 256>>>();
    k_scat<<<(ET + 255) / 256, 256>>>(eidx, ew);

    const int GEMM_BLOCKS = (NN + 63) / 64;   // 782
    const int WARP_BLOCKS = NN / 8;           // 6250 (8 warps/block)

    // layer 1
    k_gemm<<<GEMM_BLOCKS, 256>>>(x, 1, FIN, W[0], b[0] /*unused*/);
    k_att<<<WARP_BLOCKS, 256>>>(as_[0], ad_[0]);
    k_agg<<<WARP_BLOCKS, 256>>>(0);
    // layer 2
    k_gemm<<<GEMM_BLOCKS, 256>>>(x, 0, HID, W[1], b[0]);
    k_att<<<WARP_BLOCKS, 256>>>(as_[1], ad_[1]);
    k_agg<<<WARP_BLOCKS, 256>>>(1);
    // layer 3
    k_gemm<<<GEMM_BLOCKS, 256>>>(x, 0, HID, W[2], b[1]);
    k_att<<<WARP_BLOCKS, 256>>>(as_[2], ad_[2]);
    k_agg<<<WARP_BLOCKS, 256>>>(2);

    k_pool<<<(NN * 16 + 255) / 256, 256>>>(batch, b[2]);
    k_read<<<NG, 64>>>(lin_w, lin_b, outp);
}

// round 4
// speedup vs baseline: 2.6452x; 1.1061x over previous
#include <cuda_runtime.h>
#include <cuda_fp16.h>
#include <math.h>

#define NN   50000
#define NE   800000
#define ET   850000
#define FIN  128
#define HID  64
#define NG   512
#define SLOPE 0.2f
#define PRE_BLOCKS 512

// ---------------- scratch ----------------
__device__ __half g_hh[NN * HID];     // transformed features (fp16, for gather)
__device__ float g_out[NN * HID];     // normalized layer output (fp32)
__device__ float g_asrc[NN];
__device__ float g_adst[NN];
__device__ int   g_cnt[NN];
__device__ int   g_rofs[NN + 1];
__device__ int   g_pos[NN];
__device__ int   g_esrc[ET];          // src permuted by dst
__device__ float g_eatt[ET];          // eattr permuted by dst
__device__ float g_pooled[NG * HID];
__device__ float g_gcnt[NG];
__device__ float g_scal[8];           // [0]=sum(ew), [1..3]=c per layer
__device__ int   g_bsum[256];
__device__ int   g_bpre[256];
__device__ float g_part[PRE_BLOCKS];

// ---------------- fused setup: zero + c + edge-weight partial sums ----------------
__global__ void k_pre(const float* __restrict__ We0, const float* __restrict__ ae0,
                      const float* __restrict__ We1, const float* __restrict__ ae1,
                      const float* __restrict__ We2, const float* __restrict__ ae2,
                      const float* __restrict__ ew) {
    __shared__ float sm[256];
    int b = blockIdx.x, t = threadIdx.x;
    int i = b * 256 + t;
    if (i < NN) g_cnt[i] = 0;
    if (i < NG * HID) g_pooled[i] = 0.f;
    if (i < NG) g_gcnt[i] = 0.f;

    // edge-weight partial sum (grid-stride)
    float acc = 0.f;
    for (int idx = i; idx < NE; idx += PRE_BLOCKS * 256) acc += ew[idx];
    sm[t] = acc;
    __syncthreads();
    for (int off = 128; off > 0; off >>= 1) {
        if (t < off) sm[t] += sm[t + off];
        __syncthreads();
    }
    if (t == 0) g_part[b] = sm[0];
    __syncthreads();

    // blocks 0..2: per-layer scalar c = dot(We, ae)
    if (b < 3) {
        const float* We = (b == 0) ? We0 : (b == 1) ? We1 : We2;
        const float* ae = (b == 0) ? ae0 : (b == 1) ? ae1 : ae2;
        sm[t] = (t < HID) ? We[t] * ae[t] : 0.f;
        __syncthreads();
        for (int off = 128; off > 0; off >>= 1) {
            if (t < off) sm[t] += sm[t + off];
            __syncthreads();
        }
        if (t == 0) g_scal[1 + b] = sm[0];
    }
}

__global__ void k_hist(const int* __restrict__ eidx) {
    int e = blockIdx.x * blockDim.x + threadIdx.x;
    if (e >= ET) return;
    int d = (e < NE) ? eidx[NE + e] : (e - NE);
    atomicAdd(&g_cnt[d], 1);
}

// scan stage 1: per-block sums of 256 counts
__global__ void k_s1() {
    __shared__ int sh[256];
    int t = threadIdx.x;
    int i = blockIdx.x * 256 + t;
    sh[t] = (i < NN) ? g_cnt[i] : 0;
    __syncthreads();
    for (int off = 128; off > 0; off >>= 1) {
        if (t < off) sh[t] += sh[t + off];
        __syncthreads();
    }
    if (t == 0) g_bsum[blockIdx.x] = sh[0];
}

// scan stage 2: exclusive scan of block sums + finalize edge-weight sum
__global__ void k_s2(int nb) {
    __shared__ int sh[256];
    __shared__ float sf[256];
    int t = threadIdx.x;
    int v = (t < nb) ? g_bsum[t] : 0;
    sh[t] = v;
    sf[t] = g_part[t] + g_part[t + 256];
    __syncthreads();
    for (int off = 1; off < 256; off <<= 1) {
        int x = (t >= off) ? sh[t - off] : 0;
        __syncthreads();
        sh[t] += x;
        __syncthreads();
    }
    if (t < nb) g_bpre[t] = sh[t] - v;   // exclusive
    for (int off = 128; off > 0; off >>= 1) {
        if (t < off) sf[t] += sf[t + off];
        __syncthreads();
    }
    if (t == 0) g_scal[0] = sf[0];
}

// scan stage 3: per-block exclusive scan + offset -> rofs, pos
__global__ void k_s3() {
    __shared__ int sh[256];
    int t = threadIdx.x;
    int i = blockIdx.x * 256 + t;
    int v = (i < NN) ? g_cnt[i] : 0;
    sh[t] = v;
    __syncthreads();
    for (int off = 1; off < 256; off <<= 1) {
        int x = (t >= off) ? sh[t - off] : 0;
        __syncthreads();
        sh[t] += x;
        __syncthreads();
    }
    if (i < NN) {
        int r = g_bpre[blockIdx.x] + sh[t] - v;
        g_rofs[i] = r;
        g_pos[i] = r;
    }
    if (blockIdx.x == 0 && t == 0) g_rofs[NN] = ET;
}

__global__ void k_scat(const int* __restrict__ eidx, const float* __restrict__ ew) {
    int e = blockIdx.x * blockDim.x + threadIdx.x;
    if (e >= ET) return;
    int s, d;
    float a;
    if (e < NE) {
        s = eidx[e];
        d = eidx[NE + e];
        a = ew[e];
    } else {
        s = d = e - NE;
        a = g_scal[0] * (1.0f / (float)NE);
    }
    int p = atomicAdd(&g_pos[d], 1);
    g_esrc[p] = s;
    g_eatt[p] = a;
}

// ---------------- fused GEMM + attention logits ----------------
// h = relu(prev+bias)(or x) @ W ; store h as fp16 ; asrc/adst via shfl reduce.
// 64 nodes per block, 256 threads, thread = 4 nodes x 4 j, k chunked by 32.
__global__ void k_gemm(const float* __restrict__ X, int ext, int Fin,
                       const float* __restrict__ W,
                       const float* __restrict__ bias_prev,
                       const float* __restrict__ as_, const float* __restrict__ ad_) {
    __shared__ float xsT[32][68];   // [k][node]
    __shared__ float Ws[32][64];    // [k][j]
    int t = threadIdx.x;
    int jg = t & 15;                // j = jg*4
    int ng = t >> 4;                // nodes ng*4 .. ng*4+3
    int n0 = blockIdx.x * 64;

    float4 a0 = {0,0,0,0}, a1 = {0,0,0,0}, a2 = {0,0,0,0}, a3 = {0,0,0,0};

    for (int k0 = 0; k0 < Fin; k0 += 32) {
        {
            int c = t & 31, rr = t >> 5;
            for (int r = rr; r < 64; r += 8) {
                int n = n0 + r;
                float v = 0.f;
                if (n < NN) {
                    int k = k0 + c;
                    if (ext) v = X[(size_t)n * FIN + k];
                    else     v = fmaxf(g_out[(size_t)n * HID + k] + bias_prev[k], 0.f);
                }
                xsT[c][r] = v;
            }
            int j = t & 63, r4 = t >> 6;
            for (int r = r4; r < 32; r += 4)
                Ws[r][j] = W[(size_t)(k0 + r) * HID + j];
        }
        __syncthreads();

        #pragma unroll
        for (int k = 0; k < 32; k++) {
            float4 wv = *reinterpret_cast<const float4*>(&Ws[k][jg * 4]);
            float4 xv = *reinterpret_cast<const float4*>(&xsT[k][ng * 4]);
            a0.x = fmaf(xv.x, wv.x, a0.x); a0.y = fmaf(xv.x, wv.y, a0.y);
            a0.z = fmaf(xv.x, wv.z, a0.z); a0.w = fmaf(xv.x, wv.w, a0.w);
            a1.x = fmaf(xv.y, wv.x, a1.x); a1.y = fmaf(xv.y, wv.y, a1.y);
            a1.z = fmaf(xv.y, wv.z, a1.z); a1.w = fmaf(xv.y, wv.w, a1.w);
            a2.x = fmaf(xv.z, wv.x, a2.x); a2.y = fmaf(xv.z, wv.y, a2.y);
            a2.z = fmaf(xv.z, wv.z, a2.z); a2.w = fmaf(xv.z, wv.w, a2.w);
            a3.x = fmaf(xv.w, wv.x, a3.x); a3.y = fmaf(xv.w, wv.y, a3.y);
            a3.z = fmaf(xv.w, wv.z, a3.z); a3.w = fmaf(xv.w, wv.w, a3.w);
        }
        __syncthreads();
    }

    int j = jg * 4;
    int nb = n0 + ng * 4;

    // store h as fp16
    if (nb + 3 < NN) {
        __half2* p0 = reinterpret_cast<__half2*>(&g_hh[((size_t)(nb+0) << 6) + j]);
        p0[0] = __floats2half2_rn(a0.x, a0.y); p0[1] = __floats2half2_rn(a0.z, a0.w);
        __half2* p1 = reinterpret_cast<__half2*>(&g_hh[((size_t)(nb+1) << 6) + j]);
        p1[0] = __floats2half2_rn(a1.x, a1.y); p1[1] = __floats2half2_rn(a1.z, a1.w);
        __half2* p2 = reinterpret_cast<__half2*>(&g_hh[((size_t)(nb+2) << 6) + j]);
        p2[0] = __floats2half2_rn(a2.x, a2.y); p2[1] = __floats2half2_rn(a2.z, a2.w);
        __half2* p3 = reinterpret_cast<__half2*>(&g_hh[((size_t)(nb+3) << 6) + j]);
        p3[0] = __floats2half2_rn(a3.x, a3.y); p3[1] = __floats2half2_rn(a3.z, a3.w);
    } else {
        float4 aa[4] = {a0, a1, a2, a3};
        for (int m = 0; m < 4; m++) {
            if (nb + m < NN) {
                __half2* p = reinterpret_cast<__half2*>(&g_hh[((size_t)(nb+m) << 6) + j]);
                p[0] = __floats2half2_rn(aa[m].x, aa[m].y);
                p[1] = __floats2half2_rn(aa[m].z, aa[m].w);
            }
        }
    }

    // attention logits: reduce h.as_ and h.ad_ across the 16 threads of a node group
    float4 asv = *reinterpret_cast<const float4*>(&as_[j]);
    float4 adv = *reinterpret_cast<const float4*>(&ad_[j]);
    float s0 = a0.x*asv.x + a0.y*asv.y + a0.z*asv.z + a0.w*asv.w;
    float s1 = a1.x*asv.x + a1.y*asv.y + a1.z*asv.z + a1.w*asv.w;
    float s2 = a2.x*asv.x + a2.y*asv.y + a2.z*asv.z + a2.w*asv.w;
    float s3 = a3.x*asv.x + a3.y*asv.y + a3.z*asv.z + a3.w*asv.w;
    float d0 = a0.x*adv.x + a0.y*adv.y + a0.z*adv.z + a0.w*adv.w;
    float d1 = a1.x*adv.x + a1.y*adv.y + a1.z*adv.z + a1.w*adv.w;
    float d2 = a2.x*adv.x + a2.y*adv.y + a2.z*adv.z + a2.w*adv.w;
    float d3 = a3.x*adv.x + a3.y*adv.y + a3.z*adv.z + a3.w*adv.w;
    #pragma unroll
    for (int off = 8; off > 0; off >>= 1) {
        s0 += __shfl_down_sync(0xffffffffu, s0, off, 16);
        s1 += __shfl_down_sync(0xffffffffu, s1, off, 16);
        s2 += __shfl_down_sync(0xffffffffu, s2, off, 16);
        s3 += __shfl_down_sync(0xffffffffu, s3, off, 16);
        d0 += __shfl_down_sync(0xffffffffu, d0, off, 16);
        d1 += __shfl_down_sync(0xffffffffu, d1, off, 16);
        d2 += __shfl_down_sync(0xffffffffu, d2, off, 16);
        d3 += __shfl_down_sync(0xffffffffu, d3, off, 16);
    }
    if (jg == 0) {
        if (nb + 0 < NN) { g_asrc[nb+0] = s0; g_adst[nb+0] = d0; }
        if (nb + 1 < NN) { g_asrc[nb+1] = s1; g_adst[nb+1] = d1; }
        if (nb + 2 < NN) { g_asrc[nb+2] = s2; g_adst[nb+2] = d2; }
        if (nb + 3 < NN) { g_asrc[nb+3] = s3; g_adst[nb+3] = d3; }
    }
}

// ---------------- segmented aggregation: warp per dst node ----------------
// layer 2: normalized output is pooled directly (+ bias) instead of written out.
__global__ void k_agg(int layer, const int* __restrict__ batch,
                      const float* __restrict__ bias_last) {
    int n = blockIdx.x * 8 + (threadIdx.x >> 5);
    int lane = threadIdx.x & 31;
    int start = g_rofs[n], end = g_rofs[n + 1];
    float c = g_scal[1 + layer];
    float adstn = g_adst[n];

    float accx = 0.f, accy = 0.f, ssum = 0.f;

    for (int base = start; base < end; base += 32) {
        int i = base + lane;
        int s_l = 0;
        float alpha = 0.f;
        if (i < end) {
            s_l = g_esrc[i];
            float al = g_asrc[s_l] + adstn + g_eatt[i] * c;
            al = fmaxf(al, 0.f) + SLOPE * fminf(al, 0.f);
            alpha = __expf(al);
        }
        ssum += alpha;
        int cnt = min(32, end - base);
        int jj = 0;
        for (; jj + 4 <= cnt; jj += 4) {
            #pragma unroll
            for (int u = 0; u < 4; u++) {
                int   sj = __shfl_sync(0xffffffffu, s_l,   jj + u);
                float aj = __shfl_sync(0xffffffffu, alpha, jj + u);
                float2 hv = __half22float2(*reinterpret_cast<const __half2*>(
                    &g_hh[((size_t)sj << 6) + (lane << 1)]));
                accx = fmaf(aj, hv.x, accx);
                accy = fmaf(aj, hv.y, accy);
            }
        }
        for (; jj < cnt; jj++) {
            int   sj = __shfl_sync(0xffffffffu, s_l,   jj);
            float aj = __shfl_sync(0xffffffffu, alpha, jj);
            float2 hv = __half22float2(*reinterpret_cast<const __half2*>(
                &g_hh[((size_t)sj << 6) + (lane << 1)]));
            accx = fmaf(aj, hv.x, accx);
            accy = fmaf(aj, hv.y, accy);
        }
    }

    #pragma unroll
    for (int off = 16; off > 0; off >>= 1)
        ssum += __shfl_xor_sync(0xffffffffu, ssum, off);
    float inv = 1.f / (ssum + 1e-16f);
    float ox = accx * inv, oy = accy * inv;

    if (layer < 2) {
        float2 o = {ox, oy};
        *reinterpret_cast<float2*>(&g_out[((size_t)n << 6) + (lane << 1)]) = o;
    } else {
        int g = batch[n];
        float2 bb = *reinterpret_cast<const float2*>(&bias_last[lane << 1]);
        float* p = &g_pooled[((size_t)g << 6) + (lane << 1)];
        asm volatile("red.global.add.v2.f32 [%0], {%1,%2};"
                     :: "l"(p), "f"(ox + bb.x), "f"(oy + bb.y) : "memory");
        if (lane == 0) atomicAdd(&g_gcnt[g], 1.f);
    }
}

// ---------------- readout ----------------
__global__ void k_read(const float* __restrict__ lin_w,
                       const float* __restrict__ lin_b, float* __restrict__ outp) {
    __shared__ float r[64];
    int g = blockIdx.x, j = threadIdx.x;
    float cnt = fmaxf(g_gcnt[g], 1.f);
    r[j] = (g_pooled[(size_t)g * HID + j] / cnt) * lin_w[j];
    __syncthreads();
    for (int off = 32; off > 0; off >>= 1) {
        if (j < off) r[j] += r[j + off];
        __syncthreads();
    }
    if (j == 0) {
        float v = r[0] + lin_b[0];
        outp[g] = 1.f / (1.f + expf(-v));
    }
}

// ---------------- launch ----------------
extern "C" void kernel_launch(void* const* d_in, const int* in_sizes, int n_in,
                              void* d_out, int out_size) {
    const float* x     = (const float*)d_in[0];
    const int*   eidx  = (const int*)  d_in[1];
    const float* ew    = (const float*)d_in[2];
    const int*   batch = (const int*)  d_in[3];
    const float* W[3]  = {(const float*)d_in[4],  (const float*)d_in[10], (const float*)d_in[16]};
    const float* as_[3]= {(const float*)d_in[5],  (const float*)d_in[11], (const float*)d_in[17]};
    const float* ad_[3]= {(const float*)d_in[6],  (const float*)d_in[12], (const float*)d_in[18]};
    const float* We[3] = {(const float*)d_in[7],  (const float*)d_in[13], (const float*)d_in[19]};
    const float* ae[3] = {(const float*)d_in[8],  (const float*)d_in[14], (const float*)d_in[20]};
    const float* b[3]  = {(const float*)d_in[9],  (const float*)d_in[15], (const float*)d_in[21]};
    const float* lin_w = (const float*)d_in[22];
    const float* lin_b = (const float*)d_in[23];
    float* outp = (float*)d_out;

    const int NB_SCAN = (NN + 255) / 256;     // 196

    k_pre<<<PRE_BLOCKS, 256>>>(We[0], ae[0], We[1], ae[1], We[2], ae[2], ew);
    k_hist<<<(ET + 255) / 256, 256>>>(eidx);
    k_s1<<<NB_SCAN, 256>>>();
    k_s2<<<1, 256>>>(NB_SCAN);
    k_s3<<<NB_SCAN, 256>>>();
    k_scat<<<(ET + 255) / 256, 256>>>(eidx, ew);

    const int GEMM_BLOCKS = (NN + 63) / 64;   // 782
    const int WARP_BLOCKS = NN / 8;           // 6250

    k_gemm<<<GEMM_BLOCKS, 256>>>(x, 1, FIN, W[0], b[0], as_[0], ad_[0]);
    k_agg<<<WARP_BLOCKS, 256>>>(0, batch, b[2]);
    k_gemm<<<GEMM_BLOCKS, 256>>>(x, 0, HID, W[1], b[0], as_[1], ad_[1]);
    k_agg<<<WARP_BLOCKS, 256>>>(1, batch, b[2]);
    k_gemm<<<GEMM_BLOCKS, 256>>>(x, 0, HID, W[2], b[1], as_[2], ad_[2]);
    k_agg<<<WARP_BLOCKS, 256>>>(2, batch, b[2]);

    k_read<<<NG, 64>>>(lin_w, lin_b, outp);
}

// round 5
// speedup vs baseline: 2.7548x; 1.0414x over previous
#include <cuda_runtime.h>
#include <cuda_fp16.h>
#include <math.h>

#define NN   50000
#define NE   800000
#define ET   850000
#define FIN  128
#define HID  64
#define NG   512
#define SLOPE 0.2f
#define PRE_BLOCKS 512

// ---------------- scratch ----------------
__device__ __half g_hh[NN * HID];     // transformed features (fp16, gathered)
__device__ __half g_out[NN * HID];    // normalized layer output (fp16)
__device__ float g_asrc[NN];
__device__ float g_adst[NN];
__device__ int   g_cnt[NN];
__device__ int   g_rofs[NN];          // LOCAL exclusive scan (per 256-block)
__device__ int   g_pos[NN];           // mutable copy of g_rofs
__device__ int2  g_edge[ET];          // (src, eatt bits), permuted by dst
__device__ float g_pooled[NG * HID];
__device__ float g_gcnt[NG];
__device__ float g_scal[8];           // [0]=sum(ew), [1..3]=c per layer
__device__ int   g_bsum[256];
__device__ int   g_bpre[256];
__device__ float g_part[PRE_BLOCKS];

// ---------------- fused setup: zero + c + edge-weight partial sums ----------------
__global__ void k_pre(const float* __restrict__ We0, const float* __restrict__ ae0,
                      const float* __restrict__ We1, const float* __restrict__ ae1,
                      const float* __restrict__ We2, const float* __restrict__ ae2,
                      const float* __restrict__ ew) {
    __shared__ float sm[256];
    int b = blockIdx.x, t = threadIdx.x;
    int i = b * 256 + t;
    if (i < NN) g_cnt[i] = 0;
    if (i < NG * HID) g_pooled[i] = 0.f;
    if (i < NG) g_gcnt[i] = 0.f;

    float acc = 0.f;
    for (int idx = i; idx < NE; idx += PRE_BLOCKS * 256) acc += ew[idx];
    sm[t] = acc;
    __syncthreads();
    for (int off = 128; off > 0; off >>= 1) {
        if (t < off) sm[t] += sm[t + off];
        __syncthreads();
    }
    if (t == 0) g_part[b] = sm[0];
    __syncthreads();

    if (b < 3) {
        const float* We = (b == 0) ? We0 : (b == 1) ? We1 : We2;
        const float* ae = (b == 0) ? ae0 : (b == 1) ? ae1 : ae2;
        sm[t] = (t < HID) ? We[t] * ae[t] : 0.f;
        __syncthreads();
        for (int off = 128; off > 0; off >>= 1) {
            if (t < off) sm[t] += sm[t + off];
            __syncthreads();
        }
        if (t == 0) g_scal[1 + b] = sm[0];
    }
}

__global__ void k_hist(const int* __restrict__ eidx) {
    int e = blockIdx.x * blockDim.x + threadIdx.x;
    if (e >= ET) return;
    int d = (e < NE) ? eidx[NE + e] : (e - NE);
    atomicAdd(&g_cnt[d], 1);
}

// local exclusive scan per 256-block -> rofs & pos; block sums -> bsum
__global__ void k_s1() {
    __shared__ int sh[256];
    int t = threadIdx.x;
    int i = blockIdx.x * 256 + t;
    int v = (i < NN) ? g_cnt[i] : 0;
    sh[t] = v;
    __syncthreads();
    for (int off = 1; off < 256; off <<= 1) {
        int x = (t >= off) ? sh[t - off] : 0;
        __syncthreads();
        sh[t] += x;
        __syncthreads();
    }
    if (i < NN) {
        int r = sh[t] - v;          // local exclusive
        g_rofs[i] = r;
        g_pos[i] = r;
    }
    if (t == 255) g_bsum[blockIdx.x] = sh[t];   // block total
}

// exclusive scan of block sums + finalize edge-weight sum
__global__ void k_s2(int nb) {
    __shared__ int sh[256];
    __shared__ float sf[256];
    int t = threadIdx.x;
    int v = (t < nb) ? g_bsum[t] : 0;
    sh[t] = v;
    sf[t] = g_part[t] + g_part[t + 256];
    __syncthreads();
    for (int off = 1; off < 256; off <<= 1) {
        int x = (t >= off) ? sh[t - off] : 0;
        __syncthreads();
        sh[t] += x;
        __syncthreads();
    }
    if (t < nb) g_bpre[t] = sh[t] - v;
    for (int off = 128; off > 0; off >>= 1) {
        if (t < off) sf[t] += sf[t + off];
        __syncthreads();
    }
    if (t == 0) g_scal[0] = sf[0];
}

__global__ void k_scat(const int* __restrict__ eidx, const float* __restrict__ ew) {
    int e = blockIdx.x * blockDim.x + threadIdx.x;
    if (e >= ET) return;
    int s, d;
    float a;
    if (e < NE) {
        s = eidx[e];
        d = eidx[NE + e];
        a = ew[e];
    } else {
        s = d = e - NE;
        a = g_scal[0] * (1.0f / (float)NE);
    }
    int p = atomicAdd(&g_pos[d], 1) + g_bpre[d >> 8];
    g_edge[p] = make_int2(s, __float_as_int(a));
}

// ---------------- fused GEMM + attention logits ----------------
__global__ void k_gemm(const float* __restrict__ X, int ext, int Fin,
                       const float* __restrict__ W,
                       const float* __restrict__ bias_prev,
                       const float* __restrict__ as_, const float* __restrict__ ad_) {
    __shared__ float xsT[32][68];   // [k][node]
    __shared__ float Ws[32][64];    // [k][j]
    int t = threadIdx.x;
    int jg = t & 15;
    int ng = t >> 4;
    int n0 = blockIdx.x * 64;

    float4 a0 = {0,0,0,0}, a1 = {0,0,0,0}, a2 = {0,0,0,0}, a3 = {0,0,0,0};

    for (int k0 = 0; k0 < Fin; k0 += 32) {
        {
            int c = t & 31, rr = t >> 5;
            for (int r = rr; r < 64; r += 8) {
                int n = n0 + r;
                float v = 0.f;
                if (n < NN) {
                    int k = k0 + c;
                    if (ext) v = X[(size_t)n * FIN + k];
                    else     v = fmaxf(__half2float(g_out[((size_t)n << 6) + k])
                                        + bias_prev[k], 0.f);
                }
                xsT[c][r] = v;
            }
            int j = t & 63, r4 = t >> 6;
            for (int r = r4; r < 32; r += 4)
                Ws[r][j] = W[(size_t)(k0 + r) * HID + j];
        }
        __syncthreads();

        #pragma unroll
        for (int k = 0; k < 32; k++) {
            float4 wv = *reinterpret_cast<const float4*>(&Ws[k][jg * 4]);
            float4 xv = *reinterpret_cast<const float4*>(&xsT[k][ng * 4]);
            a0.x = fmaf(xv.x, wv.x, a0.x); a0.y = fmaf(xv.x, wv.y, a0.y);
            a0.z = fmaf(xv.x, wv.z, a0.z); a0.w = fmaf(xv.x, wv.w, a0.w);
            a1.x = fmaf(xv.y, wv.x, a1.x); a1.y = fmaf(xv.y, wv.y, a1.y);
            a1.z = fmaf(xv.y, wv.z, a1.z); a1.w = fmaf(xv.y, wv.w, a1.w);
            a2.x = fmaf(xv.z, wv.x, a2.x); a2.y = fmaf(xv.z, wv.y, a2.y);
            a2.z = fmaf(xv.z, wv.z, a2.z); a2.w = fmaf(xv.z, wv.w, a2.w);
            a3.x = fmaf(xv.w, wv.x, a3.x); a3.y = fmaf(xv.w, wv.y, a3.y);
            a3.z = fmaf(xv.w, wv.z, a3.z); a3.w = fmaf(xv.w, wv.w, a3.w);
        }
        __syncthreads();
    }

    int j = jg * 4;
    int nb = n0 + ng * 4;

    float4 aa[4] = {a0, a1, a2, a3};
    #pragma unroll
    for (int m = 0; m < 4; m++) {
        if (nb + m < NN) {
            __half2* p = reinterpret_cast<__half2*>(&g_hh[((size_t)(nb+m) << 6) + j]);
            p[0] = __floats2half2_rn(aa[m].x, aa[m].y);
            p[1] = __floats2half2_rn(aa[m].z, aa[m].w);
        }
    }

    float4 asv = *reinterpret_cast<const float4*>(&as_[j]);
    float4 adv = *reinterpret_cast<const float4*>(&ad_[j]);
    float s0 = a0.x*asv.x + a0.y*asv.y + a0.z*asv.z + a0.w*asv.w;
    float s1 = a1.x*asv.x + a1.y*asv.y + a1.z*asv.z + a1.w*asv.w;
    float s2 = a2.x*asv.x + a2.y*asv.y + a2.z*asv.z + a2.w*asv.w;
    float s3 = a3.x*asv.x + a3.y*asv.y + a3.z*asv.z + a3.w*asv.w;
    float d0 = a0.x*adv.x + a0.y*adv.y + a0.z*adv.z + a0.w*adv.w;
    float d1 = a1.x*adv.x + a1.y*adv.y + a1.z*adv.z + a1.w*adv.w;
    float d2 = a2.x*adv.x + a2.y*adv.y + a2.z*adv.z + a2.w*adv.w;
    float d3 = a3.x*adv.x + a3.y*adv.y + a3.z*adv.z + a3.w*adv.w;
    #pragma unroll
    for (int off = 8; off > 0; off >>= 1) {
        s0 += __shfl_down_sync(0xffffffffu, s0, off, 16);
        s1 += __shfl_down_sync(0xffffffffu, s1, off, 16);
        s2 += __shfl_down_sync(0xffffffffu, s2, off, 16);
        s3 += __shfl_down_sync(0xffffffffu, s3, off, 16);
        d0 += __shfl_down_sync(0xffffffffu, d0, off, 16);
        d1 += __shfl_down_sync(0xffffffffu, d1, off, 16);
        d2 += __shfl_down_sync(0xffffffffu, d2, off, 16);
        d3 += __shfl_down_sync(0xffffffffu, d3, off, 16);
    }
    if (jg == 0) {
        if (nb + 0 < NN) { g_asrc[nb+0] = s0; g_adst[nb+0] = d0; }
        if (nb + 1 < NN) { g_asrc[nb+1] = s1; g_adst[nb+1] = d1; }
        if (nb + 2 < NN) { g_asrc[nb+2] = s2; g_adst[nb+2] = d2; }
        if (nb + 3 < NN) { g_asrc[nb+3] = s3; g_adst[nb+3] = d3; }
    }
}

// ---------------- segmented aggregation: warp per dst node ----------------
__global__ void k_agg(int layer, const int* __restrict__ batch,
                      const float* __restrict__ bias_last) {
    int n = blockIdx.x * 8 + (threadIdx.x >> 5);
    int lane = threadIdx.x & 31;
    int bofs = g_bpre[n >> 8];
    int start = g_rofs[n] + bofs;
    int n2 = n + 1;
    int end = (n2 == NN) ? ET : g_rofs[n2] + g_bpre[n2 >> 8];
    float c = g_scal[1 + layer];
    float adstn = g_adst[n];

    float accx = 0.f, accy = 0.f, ssum = 0.f;

    for (int base = start; base < end; base += 32) {
        int i = base + lane;
        int s_l = 0;
        float alpha = 0.f;
        if (i < end) {
            int2 ev = g_edge[i];
            s_l = ev.x;
            float al = g_asrc[s_l] + adstn + __int_as_float(ev.y) * c;
            al = fmaxf(al, 0.f) + SLOPE * fminf(al, 0.f);
            alpha = __expf(al);
        }
        ssum += alpha;
        int cnt = min(32, end - base);
        int jj = 0;
        for (; jj + 4 <= cnt; jj += 4) {
            #pragma unroll
            for (int u = 0; u < 4; u++) {
                int   sj = __shfl_sync(0xffffffffu, s_l,   jj + u);
                float aj = __shfl_sync(0xffffffffu, alpha, jj + u);
                float2 hv = __half22float2(*reinterpret_cast<const __half2*>(
                    &g_hh[((size_t)sj << 6) + (lane << 1)]));
                accx = fmaf(aj, hv.x, accx);
                accy = fmaf(aj, hv.y, accy);
            }
        }
        for (; jj < cnt; jj++) {
            int   sj = __shfl_sync(0xffffffffu, s_l,   jj);
            float aj = __shfl_sync(0xffffffffu, alpha, jj);
            float2 hv = __half22float2(*reinterpret_cast<const __half2*>(
                &g_hh[((size_t)sj << 6) + (lane << 1)]));
            accx = fmaf(aj, hv.x, accx);
            accy = fmaf(aj, hv.y, accy);
        }
    }

    #pragma unroll
    for (int off = 16; off > 0; off >>= 1)
        ssum += __shfl_xor_sync(0xffffffffu, ssum, off);
    float inv = 1.f / (ssum + 1e-16f);
    float ox = accx * inv, oy = accy * inv;

    if (layer < 2) {
        *reinterpret_cast<__half2*>(&g_out[((size_t)n << 6) + (lane << 1)]) =
            __floats2half2_rn(ox, oy);
    } else {
        int g = batch[n];
        float2 bb = *reinterpret_cast<const float2*>(&bias_last[lane << 1]);
        float* p = &g_pooled[((size_t)g << 6) + (lane << 1)];
        asm volatile("red.global.add.v2.f32 [%0], {%1,%2};"
                     :: "l"(p), "f"(ox + bb.x), "f"(oy + bb.y) : "memory");
        if (lane == 0) atomicAdd(&g_gcnt[g], 1.f);
    }
}

// ---------------- readout ----------------
__global__ void k_read(const float* __restrict__ lin_w,
                       const float* __restrict__ lin_b, float* __restrict__ outp) {
    __shared__ float r[64];
    int g = blockIdx.x, j = threadIdx.x;
    float cnt = fmaxf(g_gcnt[g], 1.f);
    r[j] = (g_pooled[(size_t)g * HID + j] / cnt) * lin_w[j];
    __syncthreads();
    for (int off = 32; off > 0; off >>= 1) {
        if (j < off) r[j] += r[j + off];
        __syncthreads();
    }
    if (j == 0) {
        float v = r[0] + lin_b[0];
        outp[g] = 1.f / (1.f + expf(-v));
    }
}

// ---------------- launch ----------------
extern "C" void kernel_launch(void* const* d_in, const int* in_sizes, int n_in,
                              void* d_out, int out_size) {
    const float* x     = (const float*)d_in[0];
    const int*   eidx  = (const int*)  d_in[1];
    const float* ew    = (const float*)d_in[2];
    const int*   batch = (const int*)  d_in[3];
    const float* W[3]  = {(const float*)d_in[4],  (const float*)d_in[10], (const float*)d_in[16]};
    const float* as_[3]= {(const float*)d_in[5],  (const float*)d_in[11], (const float*)d_in[17]};
    const float* ad_[3]= {(const float*)d_in[6],  (const float*)d_in[12], (const float*)d_in[18]};
    const float* We[3] = {(const float*)d_in[7],  (const float*)d_in[13], (const float*)d_in[19]};
    const float* ae[3] = {(const float*)d_in[8],  (const float*)d_in[14], (const float*)d_in[20]};
    const float* b[3]  = {(const float*)d_in[9],  (const float*)d_in[15], (const float*)d_in[21]};
    const float* lin_w = (const float*)d_in[22];
    const float* lin_b = (const float*)d_in[23];
    float* outp = (float*)d_out;

    const int NB_SCAN = (NN + 255) / 256;     // 196

    k_pre<<<PRE_BLOCKS, 256>>>(We[0], ae[0], We[1], ae[1], We[2], ae[2], ew);
    k_hist<<<(ET + 255) / 256, 256>>>(eidx);
    k_s1<<<NB_SCAN, 256>>>();
    k_s2<<<1, 256>>>(NB_SCAN);
    k_scat<<<(ET + 255) / 256, 256>>>(eidx, ew);

    const int GEMM_BLOCKS = (NN + 63) / 64;   // 782
    const int WARP_BLOCKS = NN / 8;           // 6250

    k_gemm<<<GEMM_BLOCKS, 256>>>(x, 1, FIN, W[0], b[0], as_[0], ad_[0]);
    k_agg<<<WARP_BLOCKS, 256>>>(0, batch, b[2]);
    k_gemm<<<GEMM_BLOCKS, 256>>>(x, 0, HID, W[1], b[0], as_[1], ad_[1]);
    k_agg<<<WARP_BLOCKS, 256>>>(1, batch, b[2]);
    k_gemm<<<GEMM_BLOCKS, 256>>>(x, 0, HID, W[2], b[1], as_[2], ad_[2]);
    k_agg<<<WARP_BLOCKS, 256>>>(2, batch, b[2]);

    k_read<<<NG, 64>>>(lin_w, lin_b, outp);
}

// round 6
// speedup vs baseline: 2.8344x; 1.0289x over previous
#include <cuda_runtime.h>
#include <cuda_fp16.h>
#include <mma.h>
#include <math.h>

using namespace nvcuda;

#define NN   50000
#define NE   800000
#define ET   850000
#define FIN  128
#define HID  64
#define NG   512
#define SLOPE 0.2f
#define PRE_BLOCKS 512

// ---------------- scratch ----------------
__device__ __half g_hh[NN * HID];     // transformed features (fp16, gathered)
__device__ __half g_out[NN * HID];    // normalized layer output (fp16)
__device__ float g_asrc[NN];
__device__ float g_adst[NN];
__device__ int   g_cnt[NN];
__device__ int   g_rofs[NN];          // LOCAL exclusive scan (per 256-block)
__device__ int   g_pos[NN];
__device__ int2  g_edge[ET];          // (src, eatt bits), permuted by dst
__device__ float g_pooled[NG * HID];
__device__ float g_gcnt[NG];
__device__ float g_scal[8];           // [0]=sum(ew), [1..3]=c per layer
__device__ int   g_bsum[256];
__device__ int   g_bpre[256];
__device__ float g_part[PRE_BLOCKS];

// ---------------- fused setup ----------------
__global__ void k_pre(const float* __restrict__ We0, const float* __restrict__ ae0,
                      const float* __restrict__ We1, const float* __restrict__ ae1,
                      const float* __restrict__ We2, const float* __restrict__ ae2,
                      const float* __restrict__ ew) {
    __shared__ float sm[256];
    int b = blockIdx.x, t = threadIdx.x;
    int i = b * 256 + t;
    if (i < NN) g_cnt[i] = 1;                 // self-loop pre-counted
    if (i < NG * HID) g_pooled[i] = 0.f;
    if (i < NG) g_gcnt[i] = 0.f;

    float acc = 0.f;
    for (int idx = i; idx < NE; idx += PRE_BLOCKS * 256) acc += ew[idx];
    sm[t] = acc;
    __syncthreads();
    for (int off = 128; off > 0; off >>= 1) {
        if (t < off) sm[t] += sm[t + off];
        __syncthreads();
    }
    if (t == 0) g_part[b] = sm[0];
    __syncthreads();

    if (b < 3) {
        const float* We = (b == 0) ? We0 : (b == 1) ? We1 : We2;
        const float* ae = (b == 0) ? ae0 : (b == 1) ? ae1 : ae2;
        sm[t] = (t < HID) ? We[t] * ae[t] : 0.f;
        __syncthreads();
        for (int off = 128; off > 0; off >>= 1) {
            if (t < off) sm[t] += sm[t + off];
            __syncthreads();
        }
        if (t == 0) g_scal[1 + b] = sm[0];
    }
}

// histogram over REAL edges only (self loops pre-counted), int4 loads
__global__ void k_hist(const int* __restrict__ eidx) {
    int q = blockIdx.x * blockDim.x + threadIdx.x;
    if (q >= NE / 4) return;
    int4 d4 = reinterpret_cast<const int4*>(eidx + NE)[q];
    atomicAdd(&g_cnt[d4.x], 1);
    atomicAdd(&g_cnt[d4.y], 1);
    atomicAdd(&g_cnt[d4.z], 1);
    atomicAdd(&g_cnt[d4.w], 1);
}

// local exclusive scan per 256-block -> rofs & pos; block sums -> bsum
__global__ void k_s1() {
    __shared__ int sh[256];
    int t = threadIdx.x;
    int i = blockIdx.x * 256 + t;
    int v = (i < NN) ? g_cnt[i] : 0;
    sh[t] = v;
    __syncthreads();
    for (int off = 1; off < 256; off <<= 1) {
        int x = (t >= off) ? sh[t - off] : 0;
        __syncthreads();
        sh[t] += x;
        __syncthreads();
    }
    if (i < NN) {
        int r = sh[t] - v;
        g_rofs[i] = r;
        g_pos[i] = r;
    }
    if (t == 255) g_bsum[blockIdx.x] = sh[t];
}

// exclusive scan of block sums + finalize edge-weight sum
__global__ void k_s2(int nb) {
    __shared__ int sh[256];
    __shared__ float sf[256];
    int t = threadIdx.x;
    int v = (t < nb) ? g_bsum[t] : 0;
    sh[t] = v;
    sf[t] = g_part[t] + g_part[t + 256];
    __syncthreads();
    for (int off = 1; off < 256; off <<= 1) {
        int x = (t >= off) ? sh[t - off] : 0;
        __syncthreads();
        sh[t] += x;
        __syncthreads();
    }
    if (t < nb) g_bpre[t] = sh[t] - v;
    for (int off = 128; off > 0; off >>= 1) {
        if (t < off) sf[t] += sf[t + off];
        __syncthreads();
    }
    if (t == 0) g_scal[0] = sf[0];
}

__global__ void k_scat(const int* __restrict__ eidx, const float* __restrict__ ew) {
    int e = blockIdx.x * blockDim.x + threadIdx.x;
    if (e >= ET) return;
    int s, d;
    float a;
    if (e < NE) {
        s = eidx[e];
        d = eidx[NE + e];
        a = ew[e];
    } else {
        s = d = e - NE;
        a = g_scal[0] * (1.0f / (float)NE);
    }
    int p = atomicAdd(&g_pos[d], 1) + g_bpre[d >> 8];
    g_edge[p] = make_int2(s, __float_as_int(a));
}

// ---------------- HMMA GEMM (wmma) + attention logits ----------------
// 64 nodes x 64 outputs per block, 4 warps, fp16 inputs, fp32 accum.
#define LDA 136   // half
#define LDB 72    // half
#define LDC 68    // float

__global__ void k_gemm(const float* __restrict__ X, int ext, int Fin,
                       const float* __restrict__ W,
                       const float* __restrict__ bias_prev,
                       const float* __restrict__ as_, const float* __restrict__ ad_) {
    __shared__ __align__(16) char sbuf[18432 + 17408];
    __half* Bs = reinterpret_cast<__half*>(sbuf);            // [K][LDB]
    __half* As = reinterpret_cast<__half*>(sbuf + 18432);    // [64][LDA]
    float*  Cs = reinterpret_cast<float*>(sbuf + 18432);     // [64][LDC] (aliases As)

    int t = threadIdx.x;
    int w = t >> 5;
    int n0 = blockIdx.x * 64;

    // ---- load A (x fp32 -> fp16, or relu(g_out fp16 + bias)) ----
    if (ext) {
        int r = t >> 1;                 // node row 0..63
        int n = n0 + r;
        const float4* xrow = reinterpret_cast<const float4*>(X + (size_t)n * FIN);
        #pragma unroll
        for (int f = 0; f < 16; f++) {
            int c4 = (t & 1) * 16 + f;
            float4 v = (n < NN) ? xrow[c4] : make_float4(0, 0, 0, 0);
            __half2* p = reinterpret_cast<__half2*>(&As[r * LDA + c4 * 4]);
            p[0] = __floats2half2_rn(v.x, v.y);
            p[1] = __floats2half2_rn(v.z, v.w);
        }
    } else {
        int r = t >> 1;
        int n = n0 + r;
        int cbase = (t & 1) * 32;
        #pragma unroll
        for (int c = 0; c < 16; c++) {
            int col = cbase + c * 2;
            float2 hv = {0.f, 0.f};
            if (n < NN)
                hv = __half22float2(*reinterpret_cast<const __half2*>(
                    &g_out[((size_t)n << 6) + col]));
            float bx = bias_prev[col], by = bias_prev[col + 1];
            hv.x = fmaxf(hv.x + bx, 0.f);
            hv.y = fmaxf(hv.y + by, 0.f);
            *reinterpret_cast<__half2*>(&As[r * LDA + col]) = __floats2half2_rn(hv.x, hv.y);
        }
    }

    // ---- load B (W fp32 [K][64] -> fp16 smem) ----
    {
        int total4 = Fin * HID / 4;
        const float4* w4 = reinterpret_cast<const float4*>(W);
        for (int idx = t; idx < total4; idx += 128) {
            int r = idx >> 4;           // k row
            int c4 = idx & 15;
            float4 v = w4[idx];
            __half2* p = reinterpret_cast<__half2*>(&Bs[r * LDB + c4 * 4]);
            p[0] = __floats2half2_rn(v.x, v.y);
            p[1] = __floats2half2_rn(v.z, v.w);
        }
    }
    __syncthreads();

    // ---- MMA: warp w computes rows [16w,16w+16), all 64 cols ----
    wmma::fragment<wmma::accumulator, 16, 16, 16, float> acc[4];
    #pragma unroll
    for (int nt = 0; nt < 4; nt++) wmma::fill_fragment(acc[nt], 0.f);

    int ksteps = Fin >> 4;
    for (int kt = 0; kt < ksteps; kt++) {
        wmma::fragment<wmma::matrix_a, 16, 16, 16, __half, wmma::row_major> af;
        wmma::load_matrix_sync(af, &As[(w * 16) * LDA + kt * 16], LDA);
        #pragma unroll
        for (int nt = 0; nt < 4; nt++) {
            wmma::fragment<wmma::matrix_b, 16, 16, 16, __half, wmma::row_major> bf;
            wmma::load_matrix_sync(bf, &Bs[(kt * 16) * LDB + nt * 16], LDB);
            wmma::mma_sync(acc[nt], af, bf, acc[nt]);
        }
    }
    __syncthreads();   // As dead; Cs aliases it

    #pragma unroll
    for (int nt = 0; nt < 4; nt++)
        wmma::store_matrix_sync(&Cs[(w * 16) * LDC + nt * 16], acc[nt], LDC,
                                wmma::mem_row_major);
    __syncthreads();

    // ---- epilogue: h fp16 store + attention logits ----
    {
        int r = t >> 1;                 // node row
        int n = n0 + r;
        int cbase = (t & 1) * 32;
        float s = 0.f, d = 0.f;
        if (n < NN) {
            #pragma unroll
            for (int c = 0; c < 32; c += 2) {
                int col = cbase + c;
                float v0 = Cs[r * LDC + col];
                float v1 = Cs[r * LDC + col + 1];
                *reinterpret_cast<__half2*>(&g_hh[((size_t)n << 6) + col]) =
                    __floats2half2_rn(v0, v1);
                s = fmaf(v0, as_[col], s); s = fmaf(v1, as_[col + 1], s);
                d = fmaf(v0, ad_[col], d); d = fmaf(v1, ad_[col + 1], d);
            }
        }
        s += __shfl_xor_sync(0xffffffffu, s, 1);
        d += __shfl_xor_sync(0xffffffffu, d, 1);
        if ((t & 1) == 0 && n < NN) {
            g_asrc[n] = s;
            g_adst[n] = d;
        }
    }
}

// ---------------- segmented aggregation: warp per dst node ----------------
__global__ void k_agg(int layer, const int* __restrict__ batch,
                      const float* __restrict__ bias_last) {
    int n = blockIdx.x * 8 + (threadIdx.x >> 5);
    int lane = threadIdx.x & 31;
    int start = g_rofs[n] + g_bpre[n >> 8];
    int n2 = n + 1;
    int end = (n2 == NN) ? ET : g_rofs[n2] + g_bpre[n2 >> 8];
    float c = g_scal[1 + layer];
    float adstn = g_adst[n];

    float accx = 0.f, accy = 0.f, ssum = 0.f;

    for (int base = start; base < end; base += 32) {
        int i = base + lane;
        int s_l = 0;
        float alpha = 0.f;
        if (i < end) {
            int2 ev = g_edge[i];
            s_l = ev.x;
            float al = g_asrc[s_l] + adstn + __int_as_float(ev.y) * c;
            al = fmaxf(al, 0.f) + SLOPE * fminf(al, 0.f);
            alpha = __expf(al);
        }
        ssum += alpha;
        int cnt = min(32, end - base);
        int jj = 0;
        for (; jj + 4 <= cnt; jj += 4) {
            #pragma unroll
            for (int u = 0; u < 4; u++) {
                int   sj = __shfl_sync(0xffffffffu, s_l,   jj + u);
                float aj = __shfl_sync(0xffffffffu, alpha, jj + u);
                float2 hv = __half22float2(*reinterpret_cast<const __half2*>(
                    &g_hh[((size_t)sj << 6) + (lane << 1)]));
                accx = fmaf(aj, hv.x, accx);
                accy = fmaf(aj, hv.y, accy);
            }
        }
        for (; jj < cnt; jj++) {
            int   sj = __shfl_sync(0xffffffffu, s_l,   jj);
            float aj = __shfl_sync(0xffffffffu, alpha, jj);
            float2 hv = __half22float2(*reinterpret_cast<const __half2*>(
                &g_hh[((size_t)sj << 6) + (lane << 1)]));
            accx = fmaf(aj, hv.x, accx);
            accy = fmaf(aj, hv.y, accy);
        }
    }

    #pragma unroll
    for (int off = 16; off > 0; off >>= 1)
        ssum += __shfl_xor_sync(0xffffffffu, ssum, off);
    float inv = 1.f / (ssum + 1e-16f);
    float ox = accx * inv, oy = accy * inv;

    if (layer < 2) {
        *reinterpret_cast<__half2*>(&g_out[((size_t)n << 6) + (lane << 1)]) =
            __floats2half2_rn(ox, oy);
    } else {
        int g = batch[n];
        float2 bb = *reinterpret_cast<const float2*>(&bias_last[lane << 1]);
        float* p = &g_pooled[((size_t)g << 6) + (lane << 1)];
        asm volatile("red.global.add.v2.f32 [%0], {%1,%2};"
                     :: "l"(p), "f"(ox + bb.x), "f"(oy + bb.y) : "memory");
        if (lane == 0) atomicAdd(&g_gcnt[g], 1.f);
    }
}

// ---------------- readout ----------------
__global__ void k_read(const float* __restrict__ lin_w,
                       const float* __restrict__ lin_b, float* __restrict__ outp) {
    __shared__ float r[64];
    int g = blockIdx.x, j = threadIdx.x;
    float cnt = fmaxf(g_gcnt[g], 1.f);
    r[j] = (g_pooled[(size_t)g * HID + j] / cnt) * lin_w[j];
    __syncthreads();
    for (int off = 32; off > 0; off >>= 1) {
        if (j < off) r[j] += r[j + off];
        __syncthreads();
    }
    if (j == 0) {
        float v = r[0] + lin_b[0];
        outp[g] = 1.f / (1.f + expf(-v));
    }
}

// ---------------- launch ----------------
extern "C" void kernel_launch(void* const* d_in, const int* in_sizes, int n_in,
                              void* d_out, int out_size) {
    const float* x     = (const float*)d_in[0];
    const int*   eidx  = (const int*)  d_in[1];
    const float* ew    = (const float*)d_in[2];
    const int*   batch = (const int*)  d_in[3];
    const float* W[3]  = {(const float*)d_in[4],  (const float*)d_in[10], (const float*)d_in[16]};
    const float* as_[3]= {(const float*)d_in[5],  (const float*)d_in[11], (const float*)d_in[17]};
    const float* ad_[3]= {(const float*)d_in[6],  (const float*)d_in[12], (const float*)d_in[18]};
    const float* We[3] = {(const float*)d_in[7],  (const float*)d_in[13], (const float*)d_in[19]};
    const float* ae[3] = {(const float*)d_in[8],  (const float*)d_in[14], (const float*)d_in[20]};
    const float* b[3]  = {(const float*)d_in[9],  (const float*)d_in[15], (const float*)d_in[21]};
    const float* lin_w = (const float*)d_in[22];
    const float* lin_b = (const float*)d_in[23];
    float* outp = (float*)d_out;

    const int NB_SCAN = (NN + 255) / 256;     // 196

    k_pre<<<PRE_BLOCKS, 256>>>(We[0], ae[0], We[1], ae[1], We[2], ae[2], ew);
    k_hist<<<(NE / 4 + 255) / 256, 256>>>(eidx);
    k_s1<<<NB_SCAN, 256>>>();
    k_s2<<<1, 256>>>(NB_SCAN);
    k_scat<<<(ET + 255) / 256, 256>>>(eidx, ew);

    const int GEMM_BLOCKS = (NN + 63) / 64;   // 782
    const int WARP_BLOCKS = NN / 8;           // 6250

    k_gemm<<<GEMM_BLOCKS, 128>>>(x, 1, FIN, W[0], b[0], as_[0], ad_[0]);
    k_agg<<<WARP_BLOCKS, 256>>>(0, batch, b[2]);
    k_gemm<<<GEMM_BLOCKS, 128>>>(x, 0, HID, W[1], b[0], as_[1], ad_[1]);
    k_agg<<<WARP_BLOCKS, 256>>>(1, batch, b[2]);
    k_gemm<<<GEMM_BLOCKS, 128>>>(x, 0, HID, W[2], b[1], as_[2], ad_[2]);
    k_agg<<<WARP_BLOCKS, 256>>>(2, batch, b[2]);

    k_read<<<NG, 64>>>(lin_w, lin_b, outp);
}